// round 5
// baseline (speedup 1.0000x reference)
#include <cuda_runtime.h>
#include <cuda_bf16.h>
#include <math.h>
#include <stdint.h>

// ---------------- problem constants ----------------
#define BB     4
#define CLID   128
#define HH     256
#define WW     256
#define HWSZ   65536
#define CCAM   256
#define NTOK   8192
#define HDIM   128
#define NHEADS 4
#define MTOT   (BB*NTOK)             // 32768 tokens
#define SCALE  0.17677669529663687f  // 1/sqrt(32)

// ---------------- GEMM tiling ----------------
#define BM 128
#define BN 128
#define BK 32
#define SAW 20     // staging smem row stride (words), conflict-free
#define SVW 68     // full-width V smem row stride (words), conflict-free
#define NPART 4    // softmax partial blocks per (b,h)

// ---------------- scratch (device globals) ----------------
__device__ float  g_logit[BB*NHEADS*NTOK];
__device__ float2 g_part[BB*NHEADS*NPART];   // (local max, local sumexp)

// ---------------- helpers ----------------
__device__ __forceinline__ uint32_t f2b(float x, float y) {
    __nv_bfloat162 h = __floats2bfloat162_rn(x, y);
    return *reinterpret_cast<uint32_t*>(&h);
}
__device__ __forceinline__ float2 b2f(uint32_t u) {
    __nv_bfloat162 h = *reinterpret_cast<__nv_bfloat162*>(&u);
    return __bfloat1622float2(h);
}

#define MMA(d, a0,a1,a2,a3, b0,b1)                                              \
    asm volatile("mma.sync.aligned.m16n8k16.row.col.f32.bf16.bf16.f32 "         \
                 "{%0,%1,%2,%3},{%4,%5,%6,%7},{%8,%9},{%0,%1,%2,%3};"           \
                 : "+f"(d[0]), "+f"(d[1]), "+f"(d[2]), "+f"(d[3])               \
                 : "r"(a0), "r"(a1), "r"(a2), "r"(a3), "r"(b0), "r"(b1))

// 256 threads = 8 warps, warp grid 4(m) x 2(n); warp tile 32m x 64n
// m-frags: 2 x m16, n-frags: 8 x n8; k-steps per BK: 2

// ============================================================
// Kernel A: out = lidar + alpha*out_bias[c]
// ============================================================
__global__ void k_init(const float4* __restrict__ lidar,
                       const float*  __restrict__ alpha_p,
                       const float*  __restrict__ out_bias,
                       float4* __restrict__ out)
{
    int i = blockIdx.x * blockDim.x + threadIdx.x;
    float alpha = *alpha_p;
    int c = (i >> 14) & 127;
    float bv = alpha * out_bias[c];
    float4 v = lidar[i];
    v.x += bv; v.y += bv; v.z += bv; v.w += bv;
    out[i] = v;
}

// ============================================================
// Kernel B: fused K GEMM (tok@k_w^T, 256-deep, regs) + Q GEMM (gathered
// lidar @ q_w^T, 128-deep, regs) + logit epilogue. No K/Q scratch at all.
// ============================================================
__global__ void __launch_bounds__(256)
k_qk(const float* __restrict__ lidar,
     const float* __restrict__ tok,
     const int*   __restrict__ ind,
     const float* __restrict__ q_w,
     const float* __restrict__ k_w,
     const float* __restrict__ q_bias)
{
    __shared__ uint32_t sA[BM * SAW];
    __shared__ uint32_t sB[BN * SAW];
    __shared__ int spix[BM];

    const int m0    = blockIdx.x * BM;
    const int batch = m0 >> 13;
    const int tid   = threadIdx.x;

    if (tid < BM) {
        int tk = m0 + tid;
        int ii = ind[tk * 2 + 0], jj = ind[tk * 2 + 1];
        ii = min(max(ii, 0), HH - 1);
        jj = min(max(jj, 0), WW - 1);
        spix[tid] = ii * WW + jj;
    }
    __syncthreads();

    const int lane = tid & 31, wid = tid >> 5;
    const int wm = (wid & 3) * 32, wn = (wid >> 2) * 64;
    const int g = lane >> 2, t = lane & 3;

    // ---- phase 1: K accumulators (held through phase 2) ----
    float kacc[2][8][4];
#pragma unroll
    for (int i = 0; i < 2; i++)
#pragma unroll
        for (int j = 0; j < 8; j++)
#pragma unroll
            for (int q = 0; q < 4; q++) kacc[i][j][q] = 0.f;

    for (int k0 = 0; k0 < CCAM; k0 += BK) {
#pragma unroll
        for (int i = 0; i < 4; i++) {           // stage tok -> bf16
            int f = tid + i * 256, row = f >> 3, c = f & 7;
            float4 v = *(const float4*)(tok + (size_t)(m0 + row) * CCAM + k0 + c * 4);
            sA[row * SAW + c * 2]     = f2b(v.x, v.y);
            sA[row * SAW + c * 2 + 1] = f2b(v.z, v.w);
        }
#pragma unroll
        for (int i = 0; i < 4; i++) {           // stage k_w -> bf16
            int f = tid + i * 256, row = f >> 3, c = f & 7;
            float4 v = *(const float4*)(k_w + (size_t)row * CCAM + k0 + c * 4);
            sB[row * SAW + c * 2]     = f2b(v.x, v.y);
            sB[row * SAW + c * 2 + 1] = f2b(v.z, v.w);
        }
        __syncthreads();
#pragma unroll
        for (int kk = 0; kk < 2; kk++) {
            uint32_t br[8][2];
#pragma unroll
            for (int fn = 0; fn < 8; fn++) {
                int n = wn + fn * 8 + g;
                br[fn][0] = sB[n * SAW + kk * 8 + t];
                br[fn][1] = sB[n * SAW + kk * 8 + t + 4];
            }
#pragma unroll
            for (int fm = 0; fm < 2; fm++) {
                int m = wm + fm * 16 + g;
                uint32_t a0 = sA[m * SAW + kk * 8 + t];
                uint32_t a1 = sA[(m + 8) * SAW + kk * 8 + t];
                uint32_t a2 = sA[m * SAW + kk * 8 + t + 4];
                uint32_t a3 = sA[(m + 8) * SAW + kk * 8 + t + 4];
#pragma unroll
                for (int fn = 0; fn < 8; fn++)
                    MMA(kacc[fm][fn], a0, a1, a2, a3, br[fn][0], br[fn][1]);
            }
        }
        __syncthreads();
    }

    // ---- phase 2: Q accumulators (gathered lidar) ----
    float qacc[2][8][4];
#pragma unroll
    for (int i = 0; i < 2; i++)
#pragma unroll
        for (int j = 0; j < 8; j++)
#pragma unroll
            for (int q = 0; q < 4; q++) qacc[i][j][q] = 0.f;

    const float* lb = lidar + (size_t)batch * CLID * HWSZ;

    for (int k0 = 0; k0 < CLID; k0 += BK) {
#pragma unroll
        for (int i = 0; i < 8; i++) {           // gather: 128 rows x 16 word-cols
            int f = tid + i * 256, row = f >> 4, p = f & 15;
            const float* lp = lb + (size_t)(k0 + 2 * p) * HWSZ + spix[row];
            sA[row * SAW + p] = f2b(lp[0], lp[HWSZ]);
        }
#pragma unroll
        for (int i = 0; i < 4; i++) {           // stage q_w
            int f = tid + i * 256, row = f >> 3, c = f & 7;
            float4 v = *(const float4*)(q_w + (size_t)row * CLID + k0 + c * 4);
            sB[row * SAW + c * 2]     = f2b(v.x, v.y);
            sB[row * SAW + c * 2 + 1] = f2b(v.z, v.w);
        }
        __syncthreads();
#pragma unroll
        for (int kk = 0; kk < 2; kk++) {
            uint32_t br[8][2];
#pragma unroll
            for (int fn = 0; fn < 8; fn++) {
                int n = wn + fn * 8 + g;
                br[fn][0] = sB[n * SAW + kk * 8 + t];
                br[fn][1] = sB[n * SAW + kk * 8 + t + 4];
            }
#pragma unroll
            for (int fm = 0; fm < 2; fm++) {
                int m = wm + fm * 16 + g;
                uint32_t a0 = sA[m * SAW + kk * 8 + t];
                uint32_t a1 = sA[(m + 8) * SAW + kk * 8 + t];
                uint32_t a2 = sA[m * SAW + kk * 8 + t + 4];
                uint32_t a3 = sA[(m + 8) * SAW + kk * 8 + t + 4];
#pragma unroll
                for (int fn = 0; fn < 8; fn++)
                    MMA(qacc[fm][fn], a0, a1, a2, a3, br[fn][0], br[fn][1]);
            }
        }
        __syncthreads();
    }

    // ---- fused logit epilogue: all-register Q.K dot per head ----
#pragma unroll
    for (int fm = 0; fm < 2; fm++) {
        int m = m0 + wm + fm * 16 + g;
        int tl0 = m & (NTOK - 1), tl1 = (m + 8) & (NTOK - 1);
#pragma unroll
        for (int hoff = 0; hoff < 2; hoff++) {
            float p0 = 0.f, p1 = 0.f;
#pragma unroll
            for (int fn2 = 0; fn2 < 4; fn2++) {
                int fn = hoff * 4 + fn2;
                int n0 = wn + fn * 8 + 2 * t;
                float2 qb = *(const float2*)(q_bias + n0);
                p0 += (qacc[fm][fn][0] + qb.x) * kacc[fm][fn][0]
                    + (qacc[fm][fn][1] + qb.y) * kacc[fm][fn][1];
                p1 += (qacc[fm][fn][2] + qb.x) * kacc[fm][fn][2]
                    + (qacc[fm][fn][3] + qb.y) * kacc[fm][fn][3];
            }
            p0 += __shfl_xor_sync(0xffffffffu, p0, 1);
            p0 += __shfl_xor_sync(0xffffffffu, p0, 2);
            p1 += __shfl_xor_sync(0xffffffffu, p1, 1);
            p1 += __shfl_xor_sync(0xffffffffu, p1, 2);
            if (t == 0) {
                int h = (wn >> 5) + hoff;
                float* lpo = g_logit + (size_t)(batch * NHEADS + h) * NTOK;
                lpo[tl0] = p0 * SCALE;
                lpo[tl1] = p1 * SCALE;
            }
        }
    }
}

// ============================================================
// Kernel C: per (b,head,part) partial max + sumexp (grid = 64)
// ============================================================
__global__ void __launch_bounds__(256)
k_softred()
{
    const int bx  = blockIdx.x;            // bh*NPART + part
    const int bh  = bx >> 2, part = bx & 3;
    const float* lp = g_logit + (size_t)bh * NTOK + part * (NTOK / NPART);
    const int tid = threadIdx.x;
    __shared__ float red[256];

    float v[8];
#pragma unroll
    for (int i = 0; i < 8; i++) v[i] = lp[tid + i * 256];
    float mx = v[0];
#pragma unroll
    for (int i = 1; i < 8; i++) mx = fmaxf(mx, v[i]);
    red[tid] = mx; __syncthreads();
    for (int s = 128; s > 0; s >>= 1) {
        if (tid < s) red[tid] = fmaxf(red[tid], red[tid + s]);
        __syncthreads();
    }
    mx = red[0]; __syncthreads();

    float sum = 0.f;
#pragma unroll
    for (int i = 0; i < 8; i++) sum += expf(v[i] - mx);
    red[tid] = sum; __syncthreads();
    for (int s = 128; s > 0; s >>= 1) {
        if (tid < s) red[tid] += red[tid + s];
        __syncthreads();
    }
    if (tid == 0) g_part[bx] = make_float2(mx, red[0]);
}

// ============================================================
// Kernel D: fused V GEMM (tok@v_w^T) + attn weighting + out GEMM + scatter
// ============================================================
__global__ void __launch_bounds__(256)
k_out(const float* __restrict__ tok,
      const float* __restrict__ v_w,
      const int*   __restrict__ ind,
      const float* __restrict__ gw,
      const float* __restrict__ alpha_p,
      const float* __restrict__ out_w,
      float* __restrict__ out)
{
    __shared__ uint32_t sV[BM * SVW];      // 34816 B; first BM*SAW words alias as sA
    __shared__ uint32_t sB[BN * SAW];
    __shared__ int    spix[BM];
    __shared__ float  saw_[BM * NHEADS];
    __shared__ float2 sred[NHEADS];
    uint32_t* sA = sV;                     // time-disjoint alias

    const int m0    = blockIdx.x * BM;
    const int batch = m0 >> 13;
    const int tid   = threadIdx.x;

    if (tid < BM) {
        int tk = m0 + tid;
        int ii = ind[tk * 2 + 0], jj = ind[tk * 2 + 1];
        ii = min(max(ii, 0), HH - 1);
        jj = min(max(jj, 0), WW - 1);
        spix[tid] = ii * WW + jj;
    }
    if (tid < NHEADS) {                    // combine softmax partials
        int bh = batch * NHEADS + tid;
        float2 p[NPART];
#pragma unroll
        for (int i = 0; i < NPART; i++) p[i] = g_part[bh * NPART + i];
        float mx = p[0].x;
#pragma unroll
        for (int i = 1; i < NPART; i++) mx = fmaxf(mx, p[i].x);
        float sum = 0.f;
#pragma unroll
        for (int i = 0; i < NPART; i++) sum += p[i].y * expf(p[i].x - mx);
        sred[tid] = make_float2(mx, 1.0f / sum);
    }
    __syncthreads();
    {
        float alpha = *alpha_p;
#pragma unroll
        for (int j = 0; j < 2; j++) {
            int idx = tid + j * 256;       // 512 = 128 tokens x 4 heads
            int tl = idx & 127, h = idx >> 7;
            int tloc = (m0 & (NTOK - 1)) + tl;
            float  lt = g_logit[(size_t)(batch * NHEADS + h) * NTOK + tloc];
            float2 r  = sred[h];
            saw_[tl * NHEADS + h] = expf(lt - r.x) * r.y * gw[(size_t)batch * NTOK + tloc] * alpha;
        }
    }
    __syncthreads();

    const int lane = tid & 31, wid = tid >> 5;
    const int wm = (wid & 3) * 32, wn = (wid >> 2) * 64;
    const int g = lane >> 2, t = lane & 3;

    float acc[2][8][4];
#pragma unroll
    for (int i = 0; i < 2; i++)
#pragma unroll
        for (int j = 0; j < 8; j++)
#pragma unroll
            for (int q = 0; q < 4; q++) acc[i][j][q] = 0.f;

    // ---- phase 1: V = tok @ v_w^T (256-deep) ----
    for (int k0 = 0; k0 < CCAM; k0 += BK) {
#pragma unroll
        for (int i = 0; i < 4; i++) {
            int f = tid + i * 256, row = f >> 3, c = f & 7;
            float4 v = *(const float4*)(tok + (size_t)(m0 + row) * CCAM + k0 + c * 4);
            sA[row * SAW + c * 2]     = f2b(v.x, v.y);
            sA[row * SAW + c * 2 + 1] = f2b(v.z, v.w);
        }
#pragma unroll
        for (int i = 0; i < 4; i++) {
            int f = tid + i * 256, row = f >> 3, c = f & 7;
            float4 v = *(const float4*)(v_w + (size_t)row * CCAM + k0 + c * 4);
            sB[row * SAW + c * 2]     = f2b(v.x, v.y);
            sB[row * SAW + c * 2 + 1] = f2b(v.z, v.w);
        }
        __syncthreads();
#pragma unroll
        for (int kk = 0; kk < 2; kk++) {
            uint32_t br[8][2];
#pragma unroll
            for (int fn = 0; fn < 8; fn++) {
                int n = wn + fn * 8 + g;
                br[fn][0] = sB[n * SAW + kk * 8 + t];
                br[fn][1] = sB[n * SAW + kk * 8 + t + 4];
            }
#pragma unroll
            for (int fm = 0; fm < 2; fm++) {
                int m = wm + fm * 16 + g;
                uint32_t a0 = sA[m * SAW + kk * 8 + t];
                uint32_t a1 = sA[(m + 8) * SAW + kk * 8 + t];
                uint32_t a2 = sA[m * SAW + kk * 8 + t + 4];
                uint32_t a3 = sA[(m + 8) * SAW + kk * 8 + t + 4];
#pragma unroll
                for (int fn = 0; fn < 8; fn++)
                    MMA(acc[fm][fn], a0, a1, a2, a3, br[fn][0], br[fn][1]);
            }
        }
        __syncthreads();
    }

    // ---- weighting epilogue: sV[row][word] = bf16( attn*V ) ----
#pragma unroll
    for (int fm = 0; fm < 2; fm++) {
        int r0 = wm + fm * 16 + g;
#pragma unroll
        for (int fn = 0; fn < 8; fn++) {
            int h = (wn >> 5) + (fn >> 2);
            int wordcol = (wn >> 1) + fn * 4 + t;
            float w0 = saw_[r0 * NHEADS + h];
            float w1 = saw_[(r0 + 8) * NHEADS + h];
            sV[r0 * SVW + wordcol]       = f2b(acc[fm][fn][0] * w0, acc[fm][fn][1] * w0);
            sV[(r0 + 8) * SVW + wordcol] = f2b(acc[fm][fn][2] * w1, acc[fm][fn][3] * w1);
        }
    }
    __syncthreads();

    // ---- phase 2: y = (attn*V) @ out_w^T (128-deep), A from sV ----
#pragma unroll
    for (int i = 0; i < 2; i++)
#pragma unroll
        for (int j = 0; j < 8; j++)
#pragma unroll
            for (int q = 0; q < 4; q++) acc[i][j][q] = 0.f;

    for (int k0 = 0; k0 < HDIM; k0 += BK) {
#pragma unroll
        for (int i = 0; i < 4; i++) {          // stage out_w
            int f = tid + i * 256, row = f >> 3, c = f & 7;
            float4 v = *(const float4*)(out_w + (size_t)row * HDIM + k0 + c * 4);
            sB[row * SAW + c * 2]     = f2b(v.x, v.y);
            sB[row * SAW + c * 2 + 1] = f2b(v.z, v.w);
        }
        __syncthreads();
#pragma unroll
        for (int kk = 0; kk < 2; kk++) {
            uint32_t br[8][2];
#pragma unroll
            for (int fn = 0; fn < 8; fn++) {
                int n = wn + fn * 8 + g;
                br[fn][0] = sB[n * SAW + kk * 8 + t];
                br[fn][1] = sB[n * SAW + kk * 8 + t + 4];
            }
#pragma unroll
            for (int fm = 0; fm < 2; fm++) {
                int m = wm + fm * 16 + g;
                uint32_t a0 = sV[m * SVW + (k0 >> 1) + kk * 8 + t];
                uint32_t a1 = sV[(m + 8) * SVW + (k0 >> 1) + kk * 8 + t];
                uint32_t a2 = sV[m * SVW + (k0 >> 1) + kk * 8 + t + 4];
                uint32_t a3 = sV[(m + 8) * SVW + (k0 >> 1) + kk * 8 + t + 4];
#pragma unroll
                for (int fn = 0; fn < 8; fn++)
                    MMA(acc[fm][fn], a0, a1, a2, a3, br[fn][0], br[fn][1]);
            }
        }
        __syncthreads();
    }

    // ---- scatter-add ----
    float* ob = out + (size_t)batch * CLID * HWSZ;
#pragma unroll
    for (int fm = 0; fm < 2; fm++) {
        int ml = wm + fm * 16 + g;
        int pix0 = spix[ml], pix1 = spix[ml + 8];
#pragma unroll
        for (int fn = 0; fn < 8; fn++) {
            int col = wn + fn * 8 + 2 * t;
            atomicAdd(ob + (size_t)col * HWSZ + pix0,       acc[fm][fn][0]);
            atomicAdd(ob + (size_t)(col + 1) * HWSZ + pix0, acc[fm][fn][1]);
            atomicAdd(ob + (size_t)col * HWSZ + pix1,       acc[fm][fn][2]);
            atomicAdd(ob + (size_t)(col + 1) * HWSZ + pix1, acc[fm][fn][3]);
        }
    }
}

// ============================================================
extern "C" void kernel_launch(void* const* d_in, const int* in_sizes, int n_in,
                              void* d_out, int out_size)
{
    const float* lidar = (const float*)d_in[0];
    const float* tok   = (const float*)d_in[1];
    const int*   ind   = (const int*)  d_in[2];
    const float* gw    = (const float*)d_in[3];
    const float* alpha = (const float*)d_in[4];
    const float* q_w   = (const float*)d_in[5];
    const float* q_b   = (const float*)d_in[6];
    const float* k_w   = (const float*)d_in[7];
    const float* v_w   = (const float*)d_in[8];
    const float* o_w   = (const float*)d_in[9];
    const float* o_b   = (const float*)d_in[10];
    float* out = (float*)d_out;

    k_init<<<(BB * CLID * HWSZ) / 4 / 256, 256>>>((const float4*)lidar, alpha, o_b, (float4*)out);
    k_qk<<<MTOT / BM, 256>>>(lidar, tok, ind, q_w, k_w, q_b);
    k_softred<<<BB * NHEADS * NPART, 256>>>();
    k_out<<<MTOT / BM, 256>>>(tok, v_w, ind, gw, alpha, o_w, out);
}

// round 6
// speedup vs baseline: 1.0566x; 1.0566x over previous
#include <cuda_runtime.h>
#include <cuda_bf16.h>
#include <math.h>
#include <stdint.h>

// ---------------- problem constants ----------------
#define BB     4
#define CLID   128
#define HH     256
#define WW     256
#define HWSZ   65536
#define CCAM   256
#define NTOK   8192
#define HDIM   128
#define NHEADS 4
#define MTOT   (BB*NTOK)             // 32768 tokens
#define SCALE  0.17677669529663687f  // 1/sqrt(32)

// ---------------- GEMM tiling ----------------
#define BM 64
#define BN 128
#define BK 32
#define SAW 20          // smem row stride in words, conflict-free
#define NPART 4         // softmax partial blocks per (b,h)
#define NTILE (MTOT/BM) // 512 tiles
#define TOT4  (BB*CLID*HWSZ/4)   // 8388608 float4s
#define HALF4 (TOT4/2)

// ---------------- scratch (device globals) ----------------
__device__ uint32_t g_k[MTOT*64];            // K [32768][128] bf16 packed
__device__ uint32_t g_v[MTOT*64];            // V [32768][128] bf16 packed
__device__ float    g_logit[BB*NHEADS*NTOK];
__device__ float2   g_part[BB*NHEADS*NPART]; // (local max, local sumexp)

// ---------------- helpers ----------------
__device__ __forceinline__ uint32_t f2b(float x, float y) {
    __nv_bfloat162 h = __floats2bfloat162_rn(x, y);
    return *reinterpret_cast<uint32_t*>(&h);
}
__device__ __forceinline__ float2 b2f(uint32_t u) {
    __nv_bfloat162 h = *reinterpret_cast<__nv_bfloat162*>(&u);
    return __bfloat1622float2(h);
}

#define MMA(d, a0,a1,a2,a3, b0,b1)                                              \
    asm volatile("mma.sync.aligned.m16n8k16.row.col.f32.bf16.bf16.f32 "         \
                 "{%0,%1,%2,%3},{%4,%5,%6,%7},{%8,%9},{%0,%1,%2,%3};"           \
                 : "+f"(d[0]), "+f"(d[1]), "+f"(d[2]), "+f"(d[3])               \
                 : "r"(a0), "r"(a1), "r"(a2), "r"(a3), "r"(b0), "r"(b1))

// 256 threads = 8 warps; warp grid 2(m) x 4(n); warp tile 32m x 32n
// m-frags: 2 x m16, n-frags: 4 x n8; accs = 32 floats/thread

__device__ __forceinline__ void init_span(const float4* lidar, const float* alpha_p,
                                          const float* out_bias, float4* out,
                                          int ib, int lo, int hi, int tid)
{
    float alpha = *alpha_p;
    for (int i = lo + ib * 256 + tid; i < hi; i += NTILE * 256) {
        int c = (i >> 14) & 127;
        float bv = alpha * out_bias[c];
        float4 v = lidar[i];
        v.x += bv; v.y += bv; v.z += bv; v.w += bv;
        out[i] = v;
    }
}

// ============================================================
// Phase 1: [K GEMM tiles || dense init half A], role = blockIdx&1
// ============================================================
__global__ void __launch_bounds__(256, 2)
k_phase1(const float* __restrict__ lidar,
         const float* __restrict__ tok,
         const float* __restrict__ k_w,
         const float* __restrict__ alpha_p,
         const float* __restrict__ out_bias,
         float4* __restrict__ out)
{
    __shared__ uint32_t sA[BM * SAW];
    __shared__ uint32_t sB[BN * SAW];

    const int tid = threadIdx.x;
    if (blockIdx.x & 1) {   // init role
        init_span((const float4*)lidar, alpha_p, out_bias, out,
                  blockIdx.x >> 1, 0, HALF4, tid);
        return;
    }
    const int m0 = (blockIdx.x >> 1) * BM;
    const int lane = tid & 31, wid = tid >> 5;
    const int wm = (wid & 1) * 32, wn = (wid >> 1) * 32;
    const int g = lane >> 2, t = lane & 3;

    float acc[2][4][4];
#pragma unroll
    for (int i = 0; i < 2; i++)
#pragma unroll
        for (int j = 0; j < 4; j++)
#pragma unroll
            for (int q = 0; q < 4; q++) acc[i][j][q] = 0.f;

    for (int k0 = 0; k0 < CCAM; k0 += BK) {
#pragma unroll
        for (int i = 0; i < 2; i++) {           // stage tok tile (64x32)
            int f = tid + i * 256, row = f >> 3, c = f & 7;
            float4 v = *(const float4*)(tok + (size_t)(m0 + row) * CCAM + k0 + c * 4);
            sA[row * SAW + c * 2]     = f2b(v.x, v.y);
            sA[row * SAW + c * 2 + 1] = f2b(v.z, v.w);
        }
#pragma unroll
        for (int i = 0; i < 4; i++) {           // stage k_w tile (128x32)
            int f = tid + i * 256, row = f >> 3, c = f & 7;
            float4 v = *(const float4*)(k_w + (size_t)row * CCAM + k0 + c * 4);
            sB[row * SAW + c * 2]     = f2b(v.x, v.y);
            sB[row * SAW + c * 2 + 1] = f2b(v.z, v.w);
        }
        __syncthreads();
#pragma unroll
        for (int kk = 0; kk < 2; kk++) {
            uint32_t br[4][2];
#pragma unroll
            for (int fn = 0; fn < 4; fn++) {
                int n = wn + fn * 8 + g;
                br[fn][0] = sB[n * SAW + kk * 8 + t];
                br[fn][1] = sB[n * SAW + kk * 8 + t + 4];
            }
#pragma unroll
            for (int fm = 0; fm < 2; fm++) {
                int m = wm + fm * 16 + g;
                uint32_t a0 = sA[m * SAW + kk * 8 + t];
                uint32_t a1 = sA[(m + 8) * SAW + kk * 8 + t];
                uint32_t a2 = sA[m * SAW + kk * 8 + t + 4];
                uint32_t a3 = sA[(m + 8) * SAW + kk * 8 + t + 4];
#pragma unroll
                for (int fn = 0; fn < 4; fn++)
                    MMA(acc[fm][fn], a0, a1, a2, a3, br[fn][0], br[fn][1]);
            }
        }
        __syncthreads();
    }
#pragma unroll
    for (int fm = 0; fm < 2; fm++)
#pragma unroll
        for (int fn = 0; fn < 4; fn++) {
            int m = m0 + wm + fm * 16 + g;
            int wcol = (wn >> 1) + fn * 4 + t;
            g_k[(size_t)m * 64 + wcol]       = f2b(acc[fm][fn][0], acc[fm][fn][1]);
            g_k[(size_t)(m + 8) * 64 + wcol] = f2b(acc[fm][fn][2], acc[fm][fn][3]);
        }
}

// ============================================================
// Phase 2: [Q GEMM+logits || V GEMM || init half B], role = blockIdx%3
// ============================================================
__global__ void __launch_bounds__(256, 2)
k_phase2(const float* __restrict__ lidar,
         const float* __restrict__ tok,
         const int*   __restrict__ ind,
         const float* __restrict__ q_w,
         const float* __restrict__ v_w,
         const float* __restrict__ q_bias,
         const float* __restrict__ alpha_p,
         const float* __restrict__ out_bias,
         float4* __restrict__ out)
{
    __shared__ uint32_t sA[BM * SAW];
    __shared__ uint32_t sB[BN * SAW];
    __shared__ int spix[BM];

    const int tid  = threadIdx.x;
    const int role = blockIdx.x % 3;
    const int sub  = blockIdx.x / 3;

    if (role == 2) {   // init role
        init_span((const float4*)lidar, alpha_p, out_bias, out,
                  sub, HALF4, TOT4, tid);
        return;
    }

    const int m0    = sub * BM;
    const int batch = m0 >> 13;
    const int lane = tid & 31, wid = tid >> 5;
    const int wm = (wid & 1) * 32, wn = (wid >> 1) * 32;
    const int g = lane >> 2, t = lane & 3;

    float acc[2][4][4];
#pragma unroll
    for (int i = 0; i < 2; i++)
#pragma unroll
        for (int j = 0; j < 4; j++)
#pragma unroll
            for (int q = 0; q < 4; q++) acc[i][j][q] = 0.f;

    if (role == 1) {   // ---- V GEMM: tok @ v_w^T, write g_v ----
        for (int k0 = 0; k0 < CCAM; k0 += BK) {
#pragma unroll
            for (int i = 0; i < 2; i++) {
                int f = tid + i * 256, row = f >> 3, c = f & 7;
                float4 v = *(const float4*)(tok + (size_t)(m0 + row) * CCAM + k0 + c * 4);
                sA[row * SAW + c * 2]     = f2b(v.x, v.y);
                sA[row * SAW + c * 2 + 1] = f2b(v.z, v.w);
            }
#pragma unroll
            for (int i = 0; i < 4; i++) {
                int f = tid + i * 256, row = f >> 3, c = f & 7;
                float4 v = *(const float4*)(v_w + (size_t)row * CCAM + k0 + c * 4);
                sB[row * SAW + c * 2]     = f2b(v.x, v.y);
                sB[row * SAW + c * 2 + 1] = f2b(v.z, v.w);
            }
            __syncthreads();
#pragma unroll
            for (int kk = 0; kk < 2; kk++) {
                uint32_t br[4][2];
#pragma unroll
                for (int fn = 0; fn < 4; fn++) {
                    int n = wn + fn * 8 + g;
                    br[fn][0] = sB[n * SAW + kk * 8 + t];
                    br[fn][1] = sB[n * SAW + kk * 8 + t + 4];
                }
#pragma unroll
                for (int fm = 0; fm < 2; fm++) {
                    int m = wm + fm * 16 + g;
                    uint32_t a0 = sA[m * SAW + kk * 8 + t];
                    uint32_t a1 = sA[(m + 8) * SAW + kk * 8 + t];
                    uint32_t a2 = sA[m * SAW + kk * 8 + t + 4];
                    uint32_t a3 = sA[(m + 8) * SAW + kk * 8 + t + 4];
#pragma unroll
                    for (int fn = 0; fn < 4; fn++)
                        MMA(acc[fm][fn], a0, a1, a2, a3, br[fn][0], br[fn][1]);
                }
            }
            __syncthreads();
        }
#pragma unroll
        for (int fm = 0; fm < 2; fm++)
#pragma unroll
            for (int fn = 0; fn < 4; fn++) {
                int m = m0 + wm + fm * 16 + g;
                int wcol = (wn >> 1) + fn * 4 + t;
                g_v[(size_t)m * 64 + wcol]       = f2b(acc[fm][fn][0], acc[fm][fn][1]);
                g_v[(size_t)(m + 8) * 64 + wcol] = f2b(acc[fm][fn][2], acc[fm][fn][3]);
            }
        return;
    }

    // ---- role 0: Q GEMM (gathered lidar) + logit epilogue ----
    if (tid < BM) {
        int tk = m0 + tid;
        int ii = ind[tk * 2 + 0], jj = ind[tk * 2 + 1];
        ii = min(max(ii, 0), HH - 1);
        jj = min(max(jj, 0), WW - 1);
        spix[tid] = ii * WW + jj;
    }
    __syncthreads();

    const float* lb = lidar + (size_t)batch * CLID * HWSZ;

    for (int k0 = 0; k0 < CLID; k0 += BK) {
#pragma unroll
        for (int i = 0; i < 4; i++) {           // gather: 64 rows x 16 word-cols
            int f = tid + i * 256, row = f >> 4, p = f & 15;
            const float* lp = lb + (size_t)(k0 + 2 * p) * HWSZ + spix[row];
            sA[row * SAW + p] = f2b(lp[0], lp[HWSZ]);
        }
#pragma unroll
        for (int i = 0; i < 4; i++) {           // stage q_w (128x32)
            int f = tid + i * 256, row = f >> 3, c = f & 7;
            float4 v = *(const float4*)(q_w + (size_t)row * CLID + k0 + c * 4);
            sB[row * SAW + c * 2]     = f2b(v.x, v.y);
            sB[row * SAW + c * 2 + 1] = f2b(v.z, v.w);
        }
        __syncthreads();
#pragma unroll
        for (int kk = 0; kk < 2; kk++) {
            uint32_t br[4][2];
#pragma unroll
            for (int fn = 0; fn < 4; fn++) {
                int n = wn + fn * 8 + g;
                br[fn][0] = sB[n * SAW + kk * 8 + t];
                br[fn][1] = sB[n * SAW + kk * 8 + t + 4];
            }
#pragma unroll
            for (int fm = 0; fm < 2; fm++) {
                int m = wm + fm * 16 + g;
                uint32_t a0 = sA[m * SAW + kk * 8 + t];
                uint32_t a1 = sA[(m + 8) * SAW + kk * 8 + t];
                uint32_t a2 = sA[m * SAW + kk * 8 + t + 4];
                uint32_t a3 = sA[(m + 8) * SAW + kk * 8 + t + 4];
#pragma unroll
                for (int fn = 0; fn < 4; fn++)
                    MMA(acc[fm][fn], a0, a1, a2, a3, br[fn][0], br[fn][1]);
            }
        }
        __syncthreads();
    }

    // logit epilogue: each warp owns head h = wn>>5 for its 32 m-rows
    const int h = wn >> 5;
    float* lpo = g_logit + (size_t)(batch * NHEADS + h) * NTOK;
#pragma unroll
    for (int fm = 0; fm < 2; fm++) {
        int m = m0 + wm + fm * 16 + g;
        int tl0 = m & (NTOK - 1), tl1 = (m + 8) & (NTOK - 1);
        float p0 = 0.f, p1 = 0.f;
#pragma unroll
        for (int fn = 0; fn < 4; fn++) {
            int word = (wn >> 1) + fn * 4 + t;
            float2 k0v = b2f(g_k[(size_t)m * 64 + word]);
            float2 k1v = b2f(g_k[(size_t)(m + 8) * 64 + word]);
            int n0 = wn + fn * 8 + 2 * t;
            float2 qb = *(const float2*)(q_bias + n0);
            p0 += (acc[fm][fn][0] + qb.x) * k0v.x + (acc[fm][fn][1] + qb.y) * k0v.y;
            p1 += (acc[fm][fn][2] + qb.x) * k1v.x + (acc[fm][fn][3] + qb.y) * k1v.y;
        }
        p0 += __shfl_xor_sync(0xffffffffu, p0, 1);
        p0 += __shfl_xor_sync(0xffffffffu, p0, 2);
        p1 += __shfl_xor_sync(0xffffffffu, p1, 1);
        p1 += __shfl_xor_sync(0xffffffffu, p1, 2);
        if (t == 0) {
            lpo[tl0] = p0 * SCALE;
            lpo[tl1] = p1 * SCALE;
        }
    }
}

// ============================================================
// Kernel C: per (b,head,part) partial max + sumexp (grid = 64)
// ============================================================
__global__ void __launch_bounds__(256)
k_softred()
{
    const int bx  = blockIdx.x;
    const int bh  = bx >> 2, part = bx & 3;
    const float* lp = g_logit + (size_t)bh * NTOK + part * (NTOK / NPART);
    const int tid = threadIdx.x;
    __shared__ float red[256];

    float v[8];
#pragma unroll
    for (int i = 0; i < 8; i++) v[i] = lp[tid + i * 256];
    float mx = v[0];
#pragma unroll
    for (int i = 1; i < 8; i++) mx = fmaxf(mx, v[i]);
    red[tid] = mx; __syncthreads();
    for (int s = 128; s > 0; s >>= 1) {
        if (tid < s) red[tid] = fmaxf(red[tid], red[tid + s]);
        __syncthreads();
    }
    mx = red[0]; __syncthreads();

    float sum = 0.f;
#pragma unroll
    for (int i = 0; i < 8; i++) sum += expf(v[i] - mx);
    red[tid] = sum; __syncthreads();
    for (int s = 128; s > 0; s >>= 1) {
        if (tid < s) red[tid] += red[tid + s];
        __syncthreads();
    }
    if (tid == 0) g_part[bx] = make_float2(mx, red[0]);
}

// ============================================================
// Kernel D: attn = softmax*gw*alpha; stage attn*V from g_v;
// y = out_w @ (attn*V); atomic scatter-add into out
// ============================================================
__global__ void __launch_bounds__(256, 2)
k_out(const int*   __restrict__ ind,
      const float* __restrict__ gw,
      const float* __restrict__ alpha_p,
      const float* __restrict__ out_w,
      float* __restrict__ out)
{
    __shared__ uint32_t sA[BM * SAW];
    __shared__ uint32_t sB[BN * SAW];
    __shared__ int    spix[BM];
    __shared__ float  saw_[BM * NHEADS];
    __shared__ float2 sred[NHEADS];

    const int m0    = blockIdx.x * BM;
    const int batch = m0 >> 13;
    const int tid   = threadIdx.x;

    if (tid < BM) {
        int tk = m0 + tid;
        int ii = ind[tk * 2 + 0], jj = ind[tk * 2 + 1];
        ii = min(max(ii, 0), HH - 1);
        jj = min(max(jj, 0), WW - 1);
        spix[tid] = ii * WW + jj;
    }
    if (tid < NHEADS) {                    // combine softmax partials
        int bh = batch * NHEADS + tid;
        float2 p[NPART];
#pragma unroll
        for (int i = 0; i < NPART; i++) p[i] = g_part[bh * NPART + i];
        float mx = p[0].x;
#pragma unroll
        for (int i = 1; i < NPART; i++) mx = fmaxf(mx, p[i].x);
        float sum = 0.f;
#pragma unroll
        for (int i = 0; i < NPART; i++) sum += p[i].y * expf(p[i].x - mx);
        sred[tid] = make_float2(mx, 1.0f / sum);
    }
    __syncthreads();
    {
        float alpha = *alpha_p;
        int tl = tid & 63, h = tid >> 6;   // 256 = 64 tokens x 4 heads
        int tloc = (m0 & (NTOK - 1)) + tl;
        float  lt = g_logit[(size_t)(batch * NHEADS + h) * NTOK + tloc];
        float2 r  = sred[h];
        saw_[tl * NHEADS + h] = expf(lt - r.x) * r.y * gw[(size_t)batch * NTOK + tloc] * alpha;
    }
    __syncthreads();

    const int lane = tid & 31, wid = tid >> 5;
    const int wm = (wid & 1) * 32, wn = (wid >> 1) * 32;
    const int g = lane >> 2, t = lane & 3;

    float acc[2][4][4];
#pragma unroll
    for (int i = 0; i < 2; i++)
#pragma unroll
        for (int j = 0; j < 4; j++)
#pragma unroll
            for (int q = 0; q < 4; q++) acc[i][j][q] = 0.f;

    for (int k0 = 0; k0 < HDIM; k0 += BK) {
#pragma unroll
        for (int i = 0; i < 4; i++) {          // stage attn*V (64 rows x 16 words)
            int f = tid + i * 256, row = f >> 4, wc = f & 15;
            uint32_t u = g_v[(size_t)(m0 + row) * 64 + (k0 >> 1) + wc];
            float2 v = b2f(u);
            int h = (k0 + 2 * wc) >> 5;
            float wgt = saw_[row * NHEADS + h];
            sA[row * SAW + wc] = f2b(v.x * wgt, v.y * wgt);
        }
#pragma unroll
        for (int i = 0; i < 4; i++) {          // stage out_w (128x32)
            int f = tid + i * 256, row = f >> 3, c = f & 7;
            float4 v = *(const float4*)(out_w + (size_t)row * HDIM + k0 + c * 4);
            sB[row * SAW + c * 2]     = f2b(v.x, v.y);
            sB[row * SAW + c * 2 + 1] = f2b(v.z, v.w);
        }
        __syncthreads();
#pragma unroll
        for (int kk = 0; kk < 2; kk++) {
            uint32_t br[4][2];
#pragma unroll
            for (int fn = 0; fn < 4; fn++) {
                int n = wn + fn * 8 + g;
                br[fn][0] = sB[n * SAW + kk * 8 + t];
                br[fn][1] = sB[n * SAW + kk * 8 + t + 4];
            }
#pragma unroll
            for (int fm = 0; fm < 2; fm++) {
                int m = wm + fm * 16 + g;
                uint32_t a0 = sA[m * SAW + kk * 8 + t];
                uint32_t a1 = sA[(m + 8) * SAW + kk * 8 + t];
                uint32_t a2 = sA[m * SAW + kk * 8 + t + 4];
                uint32_t a3 = sA[(m + 8) * SAW + kk * 8 + t + 4];
#pragma unroll
                for (int fn = 0; fn < 4; fn++)
                    MMA(acc[fm][fn], a0, a1, a2, a3, br[fn][0], br[fn][1]);
            }
        }
        __syncthreads();
    }

    float* ob = out + (size_t)batch * CLID * HWSZ;
#pragma unroll
    for (int fm = 0; fm < 2; fm++) {
        int ml = wm + fm * 16 + g;
        int pix0 = spix[ml], pix1 = spix[ml + 8];
#pragma unroll
        for (int fn = 0; fn < 4; fn++) {
            int col = wn + fn * 8 + 2 * t;
            atomicAdd(ob + (size_t)col * HWSZ + pix0,       acc[fm][fn][0]);
            atomicAdd(ob + (size_t)(col + 1) * HWSZ + pix0, acc[fm][fn][1]);
            atomicAdd(ob + (size_t)col * HWSZ + pix1,       acc[fm][fn][2]);
            atomicAdd(ob + (size_t)(col + 1) * HWSZ + pix1, acc[fm][fn][3]);
        }
    }
}

// ============================================================
extern "C" void kernel_launch(void* const* d_in, const int* in_sizes, int n_in,
                              void* d_out, int out_size)
{
    const float* lidar = (const float*)d_in[0];
    const float* tok   = (const float*)d_in[1];
    const int*   ind   = (const int*)  d_in[2];
    const float* gw    = (const float*)d_in[3];
    const float* alpha = (const float*)d_in[4];
    const float* q_w   = (const float*)d_in[5];
    const float* q_b   = (const float*)d_in[6];
    const float* k_w   = (const float*)d_in[7];
    const float* v_w   = (const float*)d_in[8];
    const float* o_w   = (const float*)d_in[9];
    const float* o_b   = (const float*)d_in[10];
    float* out = (float*)d_out;

    // phase 1: K GEMM || init half A  (1024 blocks, interleaved roles)
    k_phase1<<<NTILE * 2, 256>>>(lidar, tok, k_w, alpha, o_b, (float4*)out);
    // phase 2: Q GEMM+logits || V GEMM || init half B  (1536 blocks)
    k_phase2<<<NTILE * 3, 256>>>(lidar, tok, ind, q_w, v_w, q_b, alpha, o_b, (float4*)out);
    // softmax partial reductions
    k_softred<<<BB * NHEADS * NPART, 256>>>();
    // attn*V -> out projection -> scatter-add
    k_out<<<NTILE, 256>>>(ind, gw, alpha, o_w, out);
}